// round 14
// baseline (speedup 1.0000x reference)
#include <cuda_runtime.h>
#include <cstdint>

// Problem constants
#define DDIM 512
#define KCL  2048
#define NTOT 65536

// Phase-1 tiling: CTA 128x256, 256 threads (8 warps 2Mx4N), warp 64x64,
// BK=256 int8 (256 B rows).
#define BM 128
#define BN 256
#define BK 256
#define NPASS (KCL / BN)          // 8
#define NCH   (DDIM / BK)         // 2 chunks per pass
#define TOTC  (NPASS * NCH)       // 16
#define NCAND 8

// int8 quantization scale (inputs are N(0,1); max|v| over 34M samples < 6)
#define QMAX 6.0f
#define QS   (QMAX / 127.0f)
#define QS2  (QS * QS)
#define QINV (127.0f / QMAX)

#define A_BYTES (BM * BK)                      // 32 KB
#define B_BYTES (BN * BK)                      // 64 KB
#define STAGE_BYTES (A_BYTES + B_BYTES)        // 96 KB
#define NSTAGE 2
#define SMEM_BYTES (NSTAGE * STAGE_BYTES)      // 192 KB

// Scratch (16B-aligned accumulators: the new_cluster offset in d_out is only
// 4B-aligned, which faults red.global.add.v4.f32)
__device__ float    g_c2[KCL];
__device__ uint32_t g_cand[NTOT * NCAND];
__device__ __align__(16) float g_newc[(size_t)KCL * DDIM];   // 4 MB
__device__ __align__(16) float g_cnt[KCL];
__device__ __align__(16) int8_t g_x8[(size_t)NTOT * DDIM];   // 32 MB s8
__device__ __align__(16) int8_t g_c8[(size_t)KCL * DDIM];    // 1 MB s8

// ---------------------------------------------------------------------------
__device__ __forceinline__ uint32_t smem_to_u32(const void* p) {
    uint32_t a;
    asm("{ .reg .u64 t; cvta.to.shared.u64 t, %1; cvt.u32.u64 %0, t; }"
        : "=r"(a) : "l"(p));
    return a;
}
__device__ __forceinline__ void cp16(uint32_t dst, const void* src) {
    asm volatile("cp.async.cg.shared.global [%0], [%1], 16;"
                 :: "r"(dst), "l"(src) : "memory");
}
#define CP_COMMIT() asm volatile("cp.async.commit_group;" ::: "memory")
#define CP_WAIT(n)  asm volatile("cp.async.wait_group %0;" :: "n"(n) : "memory")

__device__ __forceinline__ void ldm_x4(uint32_t addr, uint32_t& r0, uint32_t& r1,
                                       uint32_t& r2, uint32_t& r3) {
    asm volatile("ldmatrix.sync.aligned.m8n8.x4.shared.b16 {%0,%1,%2,%3}, [%4];"
                 : "=r"(r0), "=r"(r1), "=r"(r2), "=r"(r3) : "r"(addr));
}

// m16n8k32 s8 MMA, s32 accumulate (sm_80+)
__device__ __forceinline__ void mma_s8(int* c, const uint32_t* a,
                                       uint32_t b0, uint32_t b1) {
    asm volatile(
        "mma.sync.aligned.m16n8k32.row.col.s32.s8.s8.s32 "
        "{%0,%1,%2,%3}, {%4,%5,%6,%7}, {%8,%9}, {%0,%1,%2,%3};"
        : "+r"(c[0]), "+r"(c[1]), "+r"(c[2]), "+r"(c[3])
        : "r"(a[0]), "r"(a[1]), "r"(a[2]), "r"(a[3]), "r"(b0), "r"(b1));
}

// quantize one float -> s8 code (round-to-nearest, clamp +-127)
__device__ __forceinline__ uint32_t q8(float v) {
    int q = __float2int_rn(v * QINV);
    q = max(-127, min(127, q));
    return (uint32_t)q & 0xFFu;
}
__device__ __forceinline__ uint32_t pack4(float a, float b, float c, float d) {
    return q8(a) | (q8(b) << 8) | (q8(c) << 16) | (q8(d) << 24);
}

// vectorized global float reduction (dst MUST be 16B aligned)
__device__ __forceinline__ void red_v4(float* p, float a, float b, float c,
                                       float d) {
    asm volatile("red.global.add.v4.f32 [%0], {%1, %2, %3, %4};"
                 :: "l"(p), "f"(a), "f"(b), "f"(c), "f"(d) : "memory");
}

__device__ __forceinline__ bool lessVI(float v, int i, float w, int j) {
    return v < w || (v == w && i < j);
}

// ---------------------------------------------------------------------------
// Prepass: x -> s8 scratch. One thread = 16 floats -> 16 bytes.
// ---------------------------------------------------------------------------
__global__ void cvt_x_kernel(const float* __restrict__ x) {
    size_t i = (size_t)blockIdx.x * blockDim.x + threadIdx.x;
    const float4* s = (const float4*)x + 4 * i;
    uint32_t h[4];
    #pragma unroll
    for (int t = 0; t < 4; t++) {
        float4 v = s[t];
        h[t] = pack4(v.x, v.y, v.z, v.w);
    }
    *(uint4*)(g_x8 + 16 * i) = *(uint4*)h;
}

// Prepass: cluster -> s8 scratch + exact fp32 c2. One warp per row.
__global__ void c2h_kernel(const float* __restrict__ cl) {
    int row  = (blockIdx.x * blockDim.x + threadIdx.x) >> 5;
    int lane = threadIdx.x & 31;
    if (row >= KCL) return;
    const float4* r = (const float4*)(cl + (size_t)row * DDIM);
    int8_t* hdst = g_c8 + (size_t)row * DDIM;
    float s = 0.f;
    #pragma unroll
    for (int t = 0; t < 4; t++) {
        int idx = lane + 32 * t;
        float4 v = r[idx];
        s += v.x * v.x + v.y * v.y + v.z * v.z + v.w * v.w;
        *(uint32_t*)(hdst + idx * 4) = pack4(v.x, v.y, v.z, v.w);
    }
    #pragma unroll
    for (int o = 16; o; o >>= 1) s += __shfl_xor_sync(~0u, s, o);
    if (lane == 0) g_c2[row] = s;
}

// Zero the scratch accumulators + the loss slot in d_out.
__global__ void zero_kernel(float* o_loss) {
    int i = blockIdx.x * blockDim.x + threadIdx.x;
    int tot = KCL * DDIM;
    if (i < tot) g_newc[i] = 0.f;
    if (i < KCL) g_cnt[i] = 0.f;
    if (i == 0) *o_loss = 0.f;
}

// Copy scratch accumulators into the (misaligned) output region.
__global__ void copy_out_kernel(float* __restrict__ o_newc,
                                float* __restrict__ o_cnt) {
    int i = blockIdx.x * blockDim.x + threadIdx.x;
    int tot = KCL * DDIM;
    if (i < tot) o_newc[i] = g_newc[i];
    if (i < KCL) o_cnt[i] = g_cnt[i];
}

// ---------------------------------------------------------------------------
// Phase 1: int8 IMMA distance GEMM + per-lane top-2 -> per-row top-8.
// smem tile rows: 256 s8 = 256 B = 16 x 16B groups; group q of row r at
// q ^ (r & 7). A 16x32-s8 MMA tile is byte-identical to a 16x16-half tile,
// so the ldmatrix patterns from the fp16 kernel carry over unchanged.
// ---------------------------------------------------------------------------
__global__ void __launch_bounds__(256, 1)
assign_s8(void) {
    extern __shared__ char smem[];
    const uint32_t sb = smem_to_u32(smem);

    const int tid  = threadIdx.x;
    const int lane = tid & 31;
    const int wid  = tid >> 5;
    const int wm   = wid & 1;       // 2 warp rows (64 m)
    const int wn   = wid >> 1;      // 4 warp cols (64 n)
    const int g    = lane >> 2;
    const int t4   = lane & 3;
    const int m0   = blockIdx.x * BM;

    // cp.async loader for flattened chunk c (pass = c>>1, dc = c&1)
    #define LDGC(c, stg) do {                                                   \
        int _dc = (c) & (NCH - 1);                                              \
        int _ps = (c) >> 1;                                                     \
        int _d0 = _dc * BK;                                                     \
        uint32_t _sa = sb + (uint32_t)(stg) * STAGE_BYTES;                      \
        _Pragma("unroll")                                                       \
        for (int i = 0; i < 8; i++) {                                           \
            int v = tid + 256 * i, r = v >> 4, q = v & 15;                      \
            cp16(_sa + r * 256 + ((q ^ (r & 7)) * 16),                          \
                 g_x8 + (size_t)(m0 + r) * DDIM + _d0 + q * 16);                \
        }                                                                       \
        uint32_t _sbB = _sa + A_BYTES;                                          \
        _Pragma("unroll")                                                       \
        for (int i = 0; i < 16; i++) {                                          \
            int v = tid + 256 * i, r = v >> 4, q = v & 15;                      \
            cp16(_sbB + r * 256 + ((q ^ (r & 7)) * 16),                         \
                 g_c8 + (size_t)(_ps * BN + r) * DDIM + _d0 + q * 16);          \
        }                                                                       \
    } while (0)

    int acc[4][8][4];
    #pragma unroll
    for (int a = 0; a < 4; a++)
        #pragma unroll
        for (int b = 0; b < 8; b++)
            #pragma unroll
            for (int e = 0; e < 4; e++) acc[a][b][e] = 0;

    // per-slot (8 row-slots/thread) top-2 over this thread's column subset
    float bv1[8], bv2[8];
    int   bi1[8], bi2[8];
    #pragma unroll
    for (int i = 0; i < 8; i++) {
        bv1[i] = 3.4e38f; bv2[i] = 3.4e38f; bi1[i] = 0; bi2[i] = 0;
    }

    // prologue: chunk 0 in flight
    LDGC(0, 0); CP_COMMIT();

    #pragma unroll 1
    for (int it = 0; it < TOTC; it++) {
        CP_WAIT(0);          // chunk it resident
        __syncthreads();     // data visible; stage (it+1)&1 free

        if (it + 1 < TOTC) { LDGC(it + 1, (it + 1) & 1); }
        CP_COMMIT();

        const uint32_t SA = sb + (uint32_t)(it & 1) * STAGE_BYTES;
        const uint32_t SB = SA + A_BYTES;

        #pragma unroll
        for (int ks = 0; ks < 8; ks++) {
            // B fragments: 4 x ldmatrix.x4, each covers 16 n x 32 k(s8)
            uint32_t bf[8][2];
            #pragma unroll
            for (int ntp = 0; ntp < 4; ntp++) {
                int row = wn * 64 + ntp * 16 + ((lane >> 4) << 3) + (lane & 7);
                int q   = 2 * ks + ((lane >> 3) & 1);
                uint32_t addr = SB + row * 256 + ((q ^ (row & 7)) * 16);
                ldm_x4(addr, bf[2 * ntp][0], bf[2 * ntp][1],
                       bf[2 * ntp + 1][0], bf[2 * ntp + 1][1]);
            }
            #pragma unroll
            for (int mt = 0; mt < 4; mt++) {
                int row = wm * 64 + mt * 16 + (lane & 15);
                int q   = 2 * ks + (lane >> 4);
                uint32_t addr = SA + row * 256 + ((q ^ (row & 7)) * 16);
                uint32_t af[4];
                ldm_x4(addr, af[0], af[1], af[2], af[3]);
                #pragma unroll
                for (int nt = 0; nt < 8; nt++)
                    mma_s8(acc[mt][nt], af, bf[nt][0], bf[nt][1]);
            }
        }

        if ((it & (NCH - 1)) == NCH - 1) {
            // pass epilogue: d2a = c2 - 2*QS2*dot_int, fold into top-2
            const int kcb = (it >> 1) * BN + wn * 64;
            float c2v[16];
            #pragma unroll
            for (int nt = 0; nt < 8; nt++) {
                c2v[nt * 2]     = __ldg(&g_c2[kcb + nt * 8 + 2 * t4]);
                c2v[nt * 2 + 1] = __ldg(&g_c2[kcb + nt * 8 + 2 * t4 + 1]);
            }
            #pragma unroll
            for (int mt = 0; mt < 4; mt++)
                #pragma unroll
                for (int e = 0; e < 4; e++) {
                    const int rs = mt * 2 + (e >> 1);
                    #pragma unroll
                    for (int nt = 0; nt < 8; nt++) {
                        float v = fmaf(-2.f * QS2, (float)acc[mt][nt][e],
                                       c2v[nt * 2 + (e & 1)]);
                        int col = kcb + nt * 8 + 2 * t4 + (e & 1);
                        if (v < bv1[rs]) {
                            bv2[rs] = bv1[rs]; bi2[rs] = bi1[rs];
                            bv1[rs] = v;       bi1[rs] = col;
                        } else if (v < bv2[rs]) {
                            bv2[rs] = v;       bi2[rs] = col;
                        }
                    }
                }
            #pragma unroll
            for (int a = 0; a < 4; a++)
                #pragma unroll
                for (int b = 0; b < 8; b++)
                    #pragma unroll
                    for (int e = 0; e < 4; e++) acc[a][b][e] = 0;
        }
    }

    // Merge: per-lane top-2 -> smem; one thread per row picks top-8.
    __syncthreads();
    float* sv = (float*)smem;                  // [128][32]
    int*   si = (int*)(smem + 16384);          // [128][32]
    #pragma unroll
    for (int rs = 0; rs < 8; rs++) {
        int row = wm * 64 + (rs >> 1) * 16 + (rs & 1) * 8 + g;
        int e = row * 32 + wn * 8 + t4 * 2;
        sv[e]     = bv1[rs];  si[e]     = bi1[rs];
        sv[e + 1] = bv2[rs];  si[e + 1] = bi2[rs];
    }
    __syncthreads();

    if (tid < BM) {
        float vK[NCAND];
        int   iK[NCAND];
        #pragma unroll
        for (int j = 0; j < NCAND; j++) { vK[j] = 3.4e38f; iK[j] = 0x7fffffff; }
        #pragma unroll 4
        for (int e = 0; e < 32; e++) {
            float v  = sv[tid * 32 + e];
            int   ix = si[tid * 32 + e];
            if (lessVI(v, ix, vK[NCAND - 1], iK[NCAND - 1])) {
                vK[NCAND - 1] = v; iK[NCAND - 1] = ix;
                #pragma unroll
                for (int k = NCAND - 1; k > 0; k--)
                    if (lessVI(vK[k], iK[k], vK[k - 1], iK[k - 1])) {
                        float tv = vK[k]; vK[k] = vK[k - 1]; vK[k - 1] = tv;
                        int   ti = iK[k]; iK[k] = iK[k - 1]; iK[k - 1] = ti;
                    }
            }
        }
        #pragma unroll
        for (int j = 0; j < NCAND; j++)
            g_cand[(size_t)(m0 + tid) * NCAND + j] = (uint32_t)iK[j];
    }
}

// ---------------------------------------------------------------------------
// Phase 2: exact fp32 rescore of NCAND candidates + idx/loss + fused v4
// scatter into ALIGNED scratch accumulators.
// ---------------------------------------------------------------------------
__global__ void __launch_bounds__(256)
finalize_kernel(const float* __restrict__ x, const float* __restrict__ cl,
                float* __restrict__ out_idx, float* __restrict__ out_loss,
                float invN) {
    __shared__ float ls[8];
    const int tid  = threadIdx.x;
    const int lane = tid & 31;
    const int wid  = tid >> 5;
    const int row  = blockIdx.x * 8 + wid;

    const float4* X4 = (const float4*)(x + (size_t)row * DDIM);
    float4 xf[4];
    #pragma unroll
    for (int t = 0; t < 4; t++) xf[t] = X4[lane + 32 * t];

    float px = 0.f;
    #pragma unroll
    for (int t = 0; t < 4; t++)
        px += xf[t].x * xf[t].x + xf[t].y * xf[t].y +
              xf[t].z * xf[t].z + xf[t].w * xf[t].w;
    #pragma unroll
    for (int o = 16; o; o >>= 1) px += __shfl_xor_sync(~0u, px, o);
    const float x2 = px;

    float bestv = 3.4e38f;
    int   besti = 0x7fffffff;
    #pragma unroll
    for (int j = 0; j < NCAND; j++) {
        int k = (int)g_cand[(size_t)row * NCAND + j];
        const float4* C4 = (const float4*)(cl + (size_t)k * DDIM);
        float pd = 0.f;
        #pragma unroll
        for (int t = 0; t < 4; t++) {
            float4 cv = C4[lane + 32 * t];
            pd = fmaf(xf[t].x, cv.x, pd);
            pd = fmaf(xf[t].y, cv.y, pd);
            pd = fmaf(xf[t].z, cv.z, pd);
            pd = fmaf(xf[t].w, cv.w, pd);
        }
        #pragma unroll
        for (int o = 16; o; o >>= 1) pd += __shfl_xor_sync(~0u, pd, o);
        float d2 = x2 + g_c2[k] - 2.f * pd;
        if (lessVI(d2, k, bestv, besti)) { bestv = d2; besti = k; }
    }

    if (lane == 0) {
        out_idx[row] = (float)besti;
        atomicAdd(&g_cnt[besti], 1.0f);
        ls[wid] = bestv;
    }
    __syncthreads();
    if (tid == 0) {
        float s = 0.f;
        #pragma unroll
        for (int w = 0; w < 8; w++) s += ls[w];
        atomicAdd(out_loss, s * invN);
    }

    // scatter x row into g_newc[besti] (16B aligned) with vector reductions
    float* dst = g_newc + (size_t)besti * DDIM;
    #pragma unroll
    for (int t = 0; t < 4; t++) {
        int b = (lane + 32 * t) * 4;
        red_v4(dst + b, xf[t].x, xf[t].y, xf[t].z, xf[t].w);
    }
}

// ---------------------------------------------------------------------------
extern "C" void kernel_launch(void* const* d_in, const int* in_sizes, int n_in,
                              void* d_out, int out_size) {
    const float* x  = (const float*)d_in[0];
    const float* cl = (const float*)d_in[1];
    const int N = in_sizes[0] / DDIM;   // 65536
    float* out = (float*)d_out;

    // Layout: [idx (N) | loss (1) | new_cluster (K*D) | counts (K)]
    float* o_idx  = out;
    float* o_loss = out + N;
    float* o_newc = out + N + 1;
    float* o_cnt  = out + N + 1 + (size_t)KCL * DDIM;

    cudaFuncSetAttribute(assign_s8,
                         cudaFuncAttributeMaxDynamicSharedMemorySize, SMEM_BYTES);

    int nz = KCL * DDIM;
    zero_kernel<<<(nz + 255) / 256, 256>>>(o_loss);

    cvt_x_kernel<<<(int)(((size_t)N * DDIM / 16 + 255) / 256), 256>>>(x);
    c2h_kernel<<<(KCL * 32 + 255) / 256, 256>>>(cl);

    assign_s8<<<N / BM, 256, SMEM_BYTES>>>();

    finalize_kernel<<<N / 8, 256>>>(x, cl, o_idx, o_loss, 1.0f / (float)N);

    copy_out_kernel<<<(nz + 255) / 256, 256>>>(o_newc, o_cnt);
}

// round 15
// speedup vs baseline: 2.5396x; 2.5396x over previous
#include <cuda_runtime.h>
#include <cuda_fp16.h>
#include <cstdint>

// Problem constants
#define DDIM 512
#define KCL  2048
#define NTOT 65536

// Phase-1 tiling: CTA 128x128, 256 threads (8 warps 2Mx4N), warp 64x32,
// BK=64 halves (128 B rows). 2 CTAs per SM.
#define BM 128
#define BN 128
#define BK 64
#define NPASS (KCL / BN)          // 16
#define NCH   (DDIM / BK)         // 8 chunks per pass
#define TOTC  (NPASS * NCH)       // 128
#define NCAND 4

#define A_BYTES (BM * BK * 2)                  // 16 KB
#define B_BYTES (BN * BK * 2)                  // 16 KB
#define STAGE_BYTES (A_BYTES + B_BYTES)        // 32 KB
#define NSTAGE 2
#define SMEM_BYTES (NSTAGE * STAGE_BYTES)      // 64 KB -> 2 CTAs/SM

// Scratch (16B-aligned accumulators: the new_cluster offset in d_out is only
// 4B-aligned, which faults red.global.add.v4.f32)
__device__ float    g_c2[KCL];
__device__ uint32_t g_cand[NTOT * NCAND];
__device__ __align__(16) float g_newc[(size_t)KCL * DDIM];   // 4 MB
__device__ __align__(16) float g_cnt[KCL];
__device__ __align__(16) __half g_xh[(size_t)NTOT * DDIM];   // 64 MB
__device__ __align__(16) __half g_ch[(size_t)KCL * DDIM];    // 2 MB

// ---------------------------------------------------------------------------
__device__ __forceinline__ uint32_t smem_to_u32(const void* p) {
    uint32_t a;
    asm("{ .reg .u64 t; cvta.to.shared.u64 t, %1; cvt.u32.u64 %0, t; }"
        : "=r"(a) : "l"(p));
    return a;
}
__device__ __forceinline__ void cp16(uint32_t dst, const void* src) {
    asm volatile("cp.async.cg.shared.global [%0], [%1], 16;"
                 :: "r"(dst), "l"(src) : "memory");
}
#define CP_COMMIT() asm volatile("cp.async.commit_group;" ::: "memory")
#define CP_WAIT(n)  asm volatile("cp.async.wait_group %0;" :: "n"(n) : "memory")

__device__ __forceinline__ void ldm_x4(uint32_t addr, uint32_t& r0, uint32_t& r1,
                                       uint32_t& r2, uint32_t& r3) {
    asm volatile("ldmatrix.sync.aligned.m8n8.x4.shared.b16 {%0,%1,%2,%3}, [%4];"
                 : "=r"(r0), "=r"(r1), "=r"(r2), "=r"(r3) : "r"(addr));
}

// m16n8k16 fp16 MMA, fp32 accumulate
__device__ __forceinline__ void mma16(float* c, const uint32_t* a,
                                      uint32_t b0, uint32_t b1) {
    asm volatile(
        "mma.sync.aligned.m16n8k16.row.col.f32.f16.f16.f32 "
        "{%0,%1,%2,%3}, {%4,%5,%6,%7}, {%8,%9}, {%0,%1,%2,%3};"
        : "+f"(c[0]), "+f"(c[1]), "+f"(c[2]), "+f"(c[3])
        : "r"(a[0]), "r"(a[1]), "r"(a[2]), "r"(a[3]), "r"(b0), "r"(b1));
}

// vectorized global float reduction (dst MUST be 16B aligned)
__device__ __forceinline__ void red_v4(float* p, float a, float b, float c,
                                       float d) {
    asm volatile("red.global.add.v4.f32 [%0], {%1, %2, %3, %4};"
                 :: "l"(p), "f"(a), "f"(b), "f"(c), "f"(d) : "memory");
}

__device__ __forceinline__ bool lessVI(float v, int i, float w, int j) {
    return v < w || (v == w && i < j);
}

// ---------------------------------------------------------------------------
// Prepass: x -> fp16 scratch. One thread = 8 floats.
// ---------------------------------------------------------------------------
__global__ void cvt_x_kernel(const float* __restrict__ x) {
    size_t i = (size_t)blockIdx.x * blockDim.x + threadIdx.x;
    const float4* s = (const float4*)x + 2 * i;
    float4 a = s[0], b = s[1];
    __half2 h[4];
    h[0] = __floats2half2_rn(a.x, a.y);
    h[1] = __floats2half2_rn(a.z, a.w);
    h[2] = __floats2half2_rn(b.x, b.y);
    h[3] = __floats2half2_rn(b.z, b.w);
    *(uint4*)(g_xh + 8 * i) = *(uint4*)h;
}

// Prepass: cluster -> fp16 scratch + exact fp32 c2. One warp per row.
__global__ void c2h_kernel(const float* __restrict__ cl) {
    int row  = (blockIdx.x * blockDim.x + threadIdx.x) >> 5;
    int lane = threadIdx.x & 31;
    if (row >= KCL) return;
    const float4* r = (const float4*)(cl + (size_t)row * DDIM);
    __half* hdst = g_ch + (size_t)row * DDIM;
    float s = 0.f;
    #pragma unroll
    for (int t = 0; t < 4; t++) {
        int idx = lane + 32 * t;
        float4 v = r[idx];
        s += v.x * v.x + v.y * v.y + v.z * v.z + v.w * v.w;
        __half2 p[2];
        p[0] = __floats2half2_rn(v.x, v.y);
        p[1] = __floats2half2_rn(v.z, v.w);
        *(uint2*)(hdst + idx * 4) = *(uint2*)p;
    }
    #pragma unroll
    for (int o = 16; o; o >>= 1) s += __shfl_xor_sync(~0u, s, o);
    if (lane == 0) g_c2[row] = s;
}

// Zero the scratch accumulators + the loss slot in d_out.
__global__ void zero_kernel(float* o_loss) {
    int i = blockIdx.x * blockDim.x + threadIdx.x;
    int tot = KCL * DDIM;
    if (i < tot) g_newc[i] = 0.f;
    if (i < KCL) g_cnt[i] = 0.f;
    if (i == 0) *o_loss = 0.f;
}

// Copy scratch accumulators into the (misaligned) output region.
__global__ void copy_out_kernel(float* __restrict__ o_newc,
                                float* __restrict__ o_cnt) {
    int i = blockIdx.x * blockDim.x + threadIdx.x;
    int tot = KCL * DDIM;
    if (i < tot) o_newc[i] = g_newc[i];
    if (i < KCL) o_cnt[i] = g_cnt[i];
}

// ---------------------------------------------------------------------------
// Phase 1: fp16 HMMA distance GEMM + per-lane top-2 -> per-row top-4.
// smem tile rows: 64 halves = 128 B = 8 x 16B groups; group q of row r at
// q ^ (r & 7) — conflict-free for cp.async stores and ldmatrix reads.
// 2 CTAs co-resident per SM hide MMA/LDSM latency across barriers.
// ---------------------------------------------------------------------------
__global__ void __launch_bounds__(256, 2)
assign_fp16(void) {
    extern __shared__ char smem[];
    const uint32_t sb = smem_to_u32(smem);

    const int tid  = threadIdx.x;
    const int lane = tid & 31;
    const int wid  = tid >> 5;
    const int wm   = wid & 1;       // 2 warp rows (64 m)
    const int wn   = wid >> 1;      // 4 warp cols (32 n)
    const int g    = lane >> 2;
    const int t4   = lane & 3;
    const int m0   = blockIdx.x * BM;

    // cp.async loader for flattened chunk c (pass = c>>3, dc = c&7)
    #define LDGC(c, stg) do {                                                   \
        int _dc = (c) & (NCH - 1);                                              \
        int _ps = (c) >> 3;                                                     \
        int _d0 = _dc * BK;                                                     \
        uint32_t _sa = sb + (uint32_t)(stg) * STAGE_BYTES;                      \
        _Pragma("unroll")                                                       \
        for (int i = 0; i < 4; i++) {                                           \
            int v = tid + 256 * i, r = v >> 3, q = v & 7;                       \
            cp16(_sa + r * 128 + ((q ^ (r & 7)) * 16),                          \
                 g_xh + (size_t)(m0 + r) * DDIM + _d0 + q * 8);                 \
        }                                                                       \
        uint32_t _sbB = _sa + A_BYTES;                                          \
        _Pragma("unroll")                                                       \
        for (int i = 0; i < 4; i++) {                                           \
            int v = tid + 256 * i, r = v >> 3, q = v & 7;                       \
            cp16(_sbB + r * 128 + ((q ^ (r & 7)) * 16),                         \
                 g_ch + (size_t)(_ps * BN + r) * DDIM + _d0 + q * 8);           \
        }                                                                       \
    } while (0)

    float acc[4][4][4];     // 4 m-tiles x 4 n-tiles x 4 -> 64 regs
    #pragma unroll
    for (int a = 0; a < 4; a++)
        #pragma unroll
        for (int b = 0; b < 4; b++)
            #pragma unroll
            for (int e = 0; e < 4; e++) acc[a][b][e] = 0.f;

    // per-slot (8 row-slots/thread) top-2 over this thread's column subset
    float bv1[8], bv2[8];
    int   bi1[8], bi2[8];
    #pragma unroll
    for (int i = 0; i < 8; i++) {
        bv1[i] = 3.4e38f; bv2[i] = 3.4e38f; bi1[i] = 0; bi2[i] = 0;
    }

    // prologue: chunk 0 in flight
    LDGC(0, 0); CP_COMMIT();

    #pragma unroll 1
    for (int it = 0; it < TOTC; it++) {
        CP_WAIT(0);          // chunk it resident
        __syncthreads();     // data visible; stage (it+1)&1 free

        if (it + 1 < TOTC) { LDGC(it + 1, (it + 1) & 1); }
        CP_COMMIT();

        const uint32_t SA = sb + (uint32_t)(it & 1) * STAGE_BYTES;
        const uint32_t SB = SA + A_BYTES;

        #pragma unroll
        for (int ks = 0; ks < 4; ks++) {
            // B fragments: 2 x ldmatrix.x4, covering 32 n x 16 k
            uint32_t bf[4][2];
            #pragma unroll
            for (int ntp = 0; ntp < 2; ntp++) {
                int row = wn * 32 + ntp * 16 + ((lane >> 4) << 3) + (lane & 7);
                int q   = 2 * ks + ((lane >> 3) & 1);
                uint32_t addr = SB + row * 128 + ((q ^ (row & 7)) * 16);
                ldm_x4(addr, bf[2 * ntp][0], bf[2 * ntp][1],
                       bf[2 * ntp + 1][0], bf[2 * ntp + 1][1]);
            }
            #pragma unroll
            for (int mt = 0; mt < 4; mt++) {
                int row = wm * 64 + mt * 16 + (lane & 15);
                int q   = 2 * ks + (lane >> 4);
                uint32_t addr = SA + row * 128 + ((q ^ (row & 7)) * 16);
                uint32_t af[4];
                ldm_x4(addr, af[0], af[1], af[2], af[3]);
                #pragma unroll
                for (int nt = 0; nt < 4; nt++)
                    mma16(acc[mt][nt], af, bf[nt][0], bf[nt][1]);
            }
        }

        if ((it & (NCH - 1)) == NCH - 1) {
            // pass epilogue: d2a = c2 - 2*dot, fold into per-slot top-2
            const int kcb = (it >> 3) * BN + wn * 32;
            float c2v[8];
            #pragma unroll
            for (int nt = 0; nt < 4; nt++) {
                c2v[nt * 2]     = __ldg(&g_c2[kcb + nt * 8 + 2 * t4]);
                c2v[nt * 2 + 1] = __ldg(&g_c2[kcb + nt * 8 + 2 * t4 + 1]);
            }
            #pragma unroll
            for (int mt = 0; mt < 4; mt++)
                #pragma unroll
                for (int e = 0; e < 4; e++) {
                    const int rs = mt * 2 + (e >> 1);
                    #pragma unroll
                    for (int nt = 0; nt < 4; nt++) {
                        float v = fmaf(-2.f, acc[mt][nt][e],
                                       c2v[nt * 2 + (e & 1)]);
                        int col = kcb + nt * 8 + 2 * t4 + (e & 1);
                        if (v < bv1[rs]) {
                            bv2[rs] = bv1[rs]; bi2[rs] = bi1[rs];
                            bv1[rs] = v;       bi1[rs] = col;
                        } else if (v < bv2[rs]) {
                            bv2[rs] = v;       bi2[rs] = col;
                        }
                    }
                }
            #pragma unroll
            for (int a = 0; a < 4; a++)
                #pragma unroll
                for (int b = 0; b < 4; b++)
                    #pragma unroll
                    for (int e = 0; e < 4; e++) acc[a][b][e] = 0.f;
        }
    }

    // Merge: per-lane top-2 -> smem; one thread per row picks top-4.
    __syncthreads();
    float* sv = (float*)smem;                  // [128][32]
    int*   si = (int*)(smem + 16384);          // [128][32]
    #pragma unroll
    for (int rs = 0; rs < 8; rs++) {
        int row = wm * 64 + (rs >> 1) * 16 + (rs & 1) * 8 + g;
        int e = row * 32 + wn * 8 + t4 * 2;
        sv[e]     = bv1[rs];  si[e]     = bi1[rs];
        sv[e + 1] = bv2[rs];  si[e + 1] = bi2[rs];
    }
    __syncthreads();

    if (tid < BM) {
        float vK[NCAND];
        int   iK[NCAND];
        #pragma unroll
        for (int j = 0; j < NCAND; j++) { vK[j] = 3.4e38f; iK[j] = 0x7fffffff; }
        #pragma unroll 4
        for (int e = 0; e < 32; e++) {
            float v  = sv[tid * 32 + e];
            int   ix = si[tid * 32 + e];
            if (lessVI(v, ix, vK[NCAND - 1], iK[NCAND - 1])) {
                vK[NCAND - 1] = v; iK[NCAND - 1] = ix;
                #pragma unroll
                for (int k = NCAND - 1; k > 0; k--)
                    if (lessVI(vK[k], iK[k], vK[k - 1], iK[k - 1])) {
                        float tv = vK[k]; vK[k] = vK[k - 1]; vK[k - 1] = tv;
                        int   ti = iK[k]; iK[k] = iK[k - 1]; iK[k - 1] = ti;
                    }
            }
        }
        #pragma unroll
        for (int j = 0; j < NCAND; j++)
            g_cand[(size_t)(m0 + tid) * NCAND + j] = (uint32_t)iK[j];
    }
}

// ---------------------------------------------------------------------------
// Phase 2: exact fp32 rescore of NCAND candidates + idx/loss + fused v4
// scatter into ALIGNED scratch accumulators.
// ---------------------------------------------------------------------------
__global__ void __launch_bounds__(256)
finalize_kernel(const float* __restrict__ x, const float* __restrict__ cl,
                float* __restrict__ out_idx, float* __restrict__ out_loss,
                float invN) {
    __shared__ float ls[8];
    const int tid  = threadIdx.x;
    const int lane = tid & 31;
    const int wid  = tid >> 5;
    const int row  = blockIdx.x * 8 + wid;

    const float4* X4 = (const float4*)(x + (size_t)row * DDIM);
    float4 xf[4];
    #pragma unroll
    for (int t = 0; t < 4; t++) xf[t] = X4[lane + 32 * t];

    float px = 0.f;
    #pragma unroll
    for (int t = 0; t < 4; t++)
        px += xf[t].x * xf[t].x + xf[t].y * xf[t].y +
              xf[t].z * xf[t].z + xf[t].w * xf[t].w;
    #pragma unroll
    for (int o = 16; o; o >>= 1) px += __shfl_xor_sync(~0u, px, o);
    const float x2 = px;

    float bestv = 3.4e38f;
    int   besti = 0x7fffffff;
    #pragma unroll
    for (int j = 0; j < NCAND; j++) {
        int k = (int)g_cand[(size_t)row * NCAND + j];
        const float4* C4 = (const float4*)(cl + (size_t)k * DDIM);
        float pd = 0.f;
        #pragma unroll
        for (int t = 0; t < 4; t++) {
            float4 cv = C4[lane + 32 * t];
            pd = fmaf(xf[t].x, cv.x, pd);
            pd = fmaf(xf[t].y, cv.y, pd);
            pd = fmaf(xf[t].z, cv.z, pd);
            pd = fmaf(xf[t].w, cv.w, pd);
        }
        #pragma unroll
        for (int o = 16; o; o >>= 1) pd += __shfl_xor_sync(~0u, pd, o);
        float d2 = x2 + g_c2[k] - 2.f * pd;
        if (lessVI(d2, k, bestv, besti)) { bestv = d2; besti = k; }
    }

    if (lane == 0) {
        out_idx[row] = (float)besti;
        atomicAdd(&g_cnt[besti], 1.0f);
        ls[wid] = bestv;
    }
    __syncthreads();
    if (tid == 0) {
        float s = 0.f;
        #pragma unroll
        for (int w = 0; w < 8; w++) s += ls[w];
        atomicAdd(out_loss, s * invN);
    }

    // scatter x row into g_newc[besti] (16B aligned) with vector reductions
    float* dst = g_newc + (size_t)besti * DDIM;
    #pragma unroll
    for (int t = 0; t < 4; t++) {
        int b = (lane + 32 * t) * 4;
        red_v4(dst + b, xf[t].x, xf[t].y, xf[t].z, xf[t].w);
    }
}

// ---------------------------------------------------------------------------
extern "C" void kernel_launch(void* const* d_in, const int* in_sizes, int n_in,
                              void* d_out, int out_size) {
    const float* x  = (const float*)d_in[0];
    const float* cl = (const float*)d_in[1];
    const int N = in_sizes[0] / DDIM;   // 65536
    float* out = (float*)d_out;

    // Layout: [idx (N) | loss (1) | new_cluster (K*D) | counts (K)]
    float* o_idx  = out;
    float* o_loss = out + N;
    float* o_newc = out + N + 1;
    float* o_cnt  = out + N + 1 + (size_t)KCL * DDIM;

    cudaFuncSetAttribute(assign_fp16,
                         cudaFuncAttributeMaxDynamicSharedMemorySize, SMEM_BYTES);

    int nz = KCL * DDIM;
    zero_kernel<<<(nz + 255) / 256, 256>>>(o_loss);

    cvt_x_kernel<<<(int)(((size_t)N * DDIM / 8 + 255) / 256), 256>>>(x);
    c2h_kernel<<<(KCL * 32 + 255) / 256, 256>>>(cl);

    assign_fp16<<<N / BM, 256, SMEM_BYTES>>>();

    finalize_kernel<<<N / 8, 256>>>(x, cl, o_idx, o_loss, 1.0f / (float)N);

    copy_out_kernel<<<(nz + 255) / 256, 256>>>(o_newc, o_cnt);
}